// round 7
// baseline (speedup 1.0000x reference)
#include <cuda_runtime.h>
#include <math.h>

// Problem constants
#define N_POINTS 4096
#define N_VIEWS  4
#define IMG_H    128
#define IMG_W    128
#define TOPK     5
#define R2F      0.0004f     // 0.02^2

// Tile binning: 32x32 tiles of 4x4 pixels
#define TSHIFT 2
#define NTX    32
#define NTY    32
#define CAP    192           // per-bin capacity (expected max ~110)

// cos(15deg), sin(15deg)
#define CE 0.96592582628906831f
#define SE 0.25881904510252074f

// Camera axes per view (columns of R): X_view = pcd . axis + T, T = (0,0,1.5)
__constant__ float c_ax[N_VIEWS][3] = {
    {-1.f, 0.f, 0.f}, {0.f, 0.f, 1.f}, {1.f, 0.f, 0.f}, {0.f, 0.f, -1.f}};
__constant__ float c_ay[N_VIEWS][3] = {
    {0.f, CE, -SE}, {-SE, CE, 0.f}, {0.f, CE, SE}, {SE, CE, 0.f}};
__constant__ float c_az[N_VIEWS][3] = {
    {0.f, -SE, -CE}, {-CE, -SE, 0.f}, {0.f, -SE, CE}, {CE, -SE, 0.f}};

// Per-view per-tile candidate bins: (px, py, pz_ndc, color)
__device__ float4 g_bins[N_VIEWS][NTY][NTX][CAP];
__device__ int    g_cnt[N_VIEWS][NTY][NTX];   // zero-init at load; raster resets after use

// One thread per (point, view). 4 consecutive threads share a point (broadcast loads).
__global__ void prep_kernel(const float* __restrict__ pcd,
                            const float* __restrict__ displace,
                            const float* __restrict__ init_colors,
                            float* __restrict__ out_colors) {
    int t = blockIdx.x * blockDim.x + threadIdx.x;
    if (t >= N_POINTS * N_VIEWS) return;
    int n = t >> 2;
    int v = t & 3;

    float x = pcd[3 * n + 0];
    float y = pcd[3 * n + 1];
    float z = pcd[3 * n + 2];
    float col = 1.0f / (1.0f + expf(-(init_colors[n] + displace[n])));
    if (v == 0) out_colors[n] = col;

    float px = x * c_ax[v][0] + y * c_ax[v][1] + z * c_ax[v][2];
    float py = x * c_ay[v][0] + y * c_ay[v][1] + z * c_ay[v][2];
    float zv = x * c_az[v][0] + y * c_az[v][1] + z * c_az[v][2] + 1.5f;
    float pz = (zv - 0.01f) / 99.99f;
    if (pz <= 0.0f) return;

    // pixel range covered: xf(xi) = 1 - (2xi+1)/128 => xi in [(1-px-r)*64-.5, (1-px+r)*64-.5]
    const float rexp = 0.0201f;   // radius + epsilon (conservative bbox)
    float xlo_f = (1.0f - px - rexp) * 64.0f - 0.5f;
    float xhi_f = (1.0f - px + rexp) * 64.0f - 0.5f;
    float ylo_f = (1.0f - py - rexp) * 64.0f - 0.5f;
    float yhi_f = (1.0f - py + rexp) * 64.0f - 0.5f;
    int ilo = max(0,   (int)ceilf(xlo_f));
    int ihi = min(127, (int)floorf(xhi_f));
    int jlo = max(0,   (int)ceilf(ylo_f));
    int jhi = min(127, (int)floorf(yhi_f));
    if (ilo > ihi || jlo > jhi) return;

    // disk bbox spans at most 3 pixels per axis -> at most 2 tiles per axis
    int txlo = ilo >> TSHIFT, txhi = ihi >> TSHIFT;
    int tylo = jlo >> TSHIFT, tyhi = jhi >> TSHIFT;
    bool x2 = (txhi != txlo);
    bool y2 = (tyhi != tylo);
    float4 rec = make_float4(px, py, pz, col);

    // Independent atomics (latency overlapped), then predicated stores
    int s00 =              atomicAdd(&g_cnt[v][tylo][txlo], 1);
    int s01 = x2         ? atomicAdd(&g_cnt[v][tylo][txhi], 1) : CAP;
    int s10 = y2         ? atomicAdd(&g_cnt[v][tyhi][txlo], 1) : CAP;
    int s11 = (x2 && y2) ? atomicAdd(&g_cnt[v][tyhi][txhi], 1) : CAP;
    if (s00 < CAP) g_bins[v][tylo][txlo][s00] = rec;
    if (s01 < CAP) g_bins[v][tylo][txhi][s01] = rec;
    if (s10 < CAP) g_bins[v][tyhi][txlo][s10] = rec;
    if (s11 < CAP) g_bins[v][tyhi][txhi][s11] = rec;
}

// Block = 64 threads = 2x2 quad of 4x4-px tiles; thread tid: sub-tile s=tid>>4,
// local pixel l=tid&15. No slicing, no merge: each thread scans only its bin.
__global__ void __launch_bounds__(64) raster_kernel(float* __restrict__ out) {
    __shared__ float4 s_cand[4][CAP];
    __shared__ int s_m[4];

    const int v   = blockIdx.z;
    const int bx  = blockIdx.x;     // 0..15 (quad col)
    const int by  = blockIdx.y;     // 0..15 (quad row)
    const int tid = threadIdx.x;
    const int s   = tid >> 4;       // sub-tile 0..3
    const int l   = tid & 15;       // pixel within 4x4

    // load the 4 bin counts
    if (tid < 4) {
        int ttx = bx * 2 + (tid & 1);
        int tty = by * 2 + (tid >> 1);
        int c = g_cnt[v][tty][ttx];
        s_m[tid] = (c > CAP) ? CAP : c;
        g_cnt[v][tty][ttx] = 0;     // reset for next graph replay
    }
    __syncthreads();

    // cooperative staging of all 4 bins
#pragma unroll
    for (int s2 = 0; s2 < 4; s2++) {
        int mm = s_m[s2];
        const float4* __restrict__ src =
            g_bins[v][by * 2 + (s2 >> 1)][bx * 2 + (s2 & 1)];
        for (int j = tid; j < mm; j += 64) s_cand[s2][j] = src[j];
    }
    __syncthreads();

    const int ttx = bx * 2 + (s & 1);
    const int tty = by * 2 + (s >> 1);
    const int xi = ttx * 4 + (l & 3);
    const int yi = tty * 4 + (l >> 2);
    const float inv128 = 0.0078125f;
    const float xf = 1.0f - (float)(2 * xi + 1) * inv128;
    const float yf = 1.0f - (float)(2 * yi + 1) * inv128;

    const float INF = __int_as_float(0x7f800000);
    float zk[TOPK], ak[TOPK], ck[TOPK];
#pragma unroll
    for (int k = 0; k < TOPK; k++) { zk[k] = INF; ak[k] = 0.0f; ck[k] = 0.0f; }

    const int m = s_m[s];
    const float4* cand = s_cand[s];
#pragma unroll 4
    for (int j = 0; j < m; j++) {
        float4 p = cand[j];
        float dx = p.x - xf;
        float dy = p.y - yf;
        float d2 = fmaf(dx, dx, dy * dy);
        if (d2 < R2F) {
            float nz = p.z;
            float na = 1.0f - d2 / R2F;
            float nc = p.w;
            // sorted insertion by z ascending (keep 5 smallest)
#pragma unroll
            for (int k = 0; k < TOPK; k++) {
                if (nz < zk[k]) {
                    float t;
                    t = zk[k]; zk[k] = nz; nz = t;
                    t = ak[k]; ak[k] = na; na = t;
                    t = ck[k]; ck[k] = nc; nc = t;
                }
            }
        }
    }

    // front-to-back over-composite (empty slots contribute 0)
    float trans = 1.0f, pixv = 0.0f;
#pragma unroll
    for (int k = 0; k < TOPK; k++) {
        pixv += ak[k] * trans * ck[k];
        trans *= (1.0f - ak[k]);
    }

    int base = (((v * IMG_H) + yi) * IMG_W + xi) * 3;
    out[base + 0] = pixv;
    out[base + 1] = pixv;
    out[base + 2] = pixv;
}

extern "C" void kernel_launch(void* const* d_in, const int* in_sizes, int n_in,
                              void* d_out, int out_size) {
    const float* pcd         = (const float*)d_in[0];
    const float* displace    = (const float*)d_in[1];
    const float* init_colors = (const float*)d_in[2];
    float* out = (float*)d_out;

    // colors_ tail lives after the 4*128*128*3 image block
    float* out_colors = out + (size_t)N_VIEWS * IMG_H * IMG_W * 3;

    prep_kernel<<<(N_POINTS * N_VIEWS + 127) / 128, 128>>>(pcd, displace, init_colors, out_colors);

    dim3 grid(NTX / 2, NTY / 2, N_VIEWS);
    raster_kernel<<<grid, 64>>>(out);
}

// round 8
// speedup vs baseline: 1.2116x; 1.2116x over previous
#include <cuda_runtime.h>
#include <math.h>

// Problem constants
#define N_POINTS 4096
#define N_VIEWS  4
#define IMG_H    128
#define IMG_W    128
#define N_PIX    (N_VIEWS * IMG_H * IMG_W)   // 65536
#define TOPK     5
#define R2F      0.0004f     // 0.02^2
#define CAP      40          // per-pixel hit capacity (avg ~1, max ~18)

// cos(15deg), sin(15deg)
#define CE 0.96592582628906831f
#define SE 0.25881904510252074f

// Camera axes per view (columns of R): X_view = pcd . axis + T, T = (0,0,1.5)
__constant__ float c_ax[N_VIEWS][3] = {
    {-1.f, 0.f, 0.f}, {0.f, 0.f, 1.f}, {1.f, 0.f, 0.f}, {0.f, 0.f, -1.f}};
__constant__ float c_ay[N_VIEWS][3] = {
    {0.f, CE, -SE}, {-SE, CE, 0.f}, {0.f, CE, SE}, {SE, CE, 0.f}};
__constant__ float c_az[N_VIEWS][3] = {
    {0.f, -SE, -CE}, {-CE, -SE, 0.f}, {0.f, -SE, CE}, {CE, -SE, 0.f}};

// Per-pixel hit lists: (z, alpha, color, pad). ~42 MB device-global scratch.
__device__ float4 g_hits[N_PIX][CAP];
__device__ int    g_hcnt[N_PIX];      // zero-init at load; raster resets after read

// One thread per (point, view). 4 consecutive threads share a point.
__global__ void prep_kernel(const float* __restrict__ pcd,
                            const float* __restrict__ displace,
                            const float* __restrict__ init_colors,
                            float* __restrict__ out_colors) {
    int t = blockIdx.x * blockDim.x + threadIdx.x;
    if (t >= N_POINTS * N_VIEWS) return;
    int n = t >> 2;
    int v = t & 3;

    float x = pcd[3 * n + 0];
    float y = pcd[3 * n + 1];
    float z = pcd[3 * n + 2];
    float col = 1.0f / (1.0f + expf(-(init_colors[n] + displace[n])));
    if (v == 0) out_colors[n] = col;

    float px = x * c_ax[v][0] + y * c_ax[v][1] + z * c_ax[v][2];
    float py = x * c_ay[v][0] + y * c_ay[v][1] + z * c_ay[v][2];
    float zv = x * c_az[v][0] + y * c_az[v][1] + z * c_az[v][2] + 1.5f;
    float pz = (zv - 0.01f) / 99.99f;
    if (pz <= 0.0f) return;

    // pixel-center range covered by the disk bbox:
    // xf(xi) = 1 - (2xi+1)/128  =>  xi in [(1-px-r)*64-0.5, (1-px+r)*64-0.5]
    const float rexp = 0.0201f;
    int ilo = max(0,   (int)ceilf ((1.0f - px - rexp) * 64.0f - 0.5f));
    int ihi = min(127, (int)floorf((1.0f - px + rexp) * 64.0f - 0.5f));
    int jlo = max(0,   (int)ceilf ((1.0f - py - rexp) * 64.0f - 0.5f));
    int jhi = min(127, (int)floorf((1.0f - py + rexp) * 64.0f - 0.5f));

    const float inv128 = 0.0078125f;
    for (int yi = jlo; yi <= jhi; yi++) {
        float yf = 1.0f - (float)(2 * yi + 1) * inv128;
        float dy = py - yf;
        float dy2 = dy * dy;
        for (int xi = ilo; xi <= ihi; xi++) {
            float xf = 1.0f - (float)(2 * xi + 1) * inv128;
            float dx = px - xf;
            float d2 = fmaf(dx, dx, dy2);
            if (d2 < R2F) {
                int p = ((v * IMG_H) + yi) * IMG_W + xi;
                int s = atomicAdd(&g_hcnt[p], 1);
                if (s < CAP)
                    g_hits[p][s] = make_float4(pz, 1.0f - d2 / R2F, col, 0.0f);
            }
        }
    }
}

// One thread per pixel: gather own hits, top-5 by z, over-composite.
__global__ void __launch_bounds__(256) raster_kernel(float* __restrict__ out) {
    int p = blockIdx.x * 256 + threadIdx.x;
    if (p >= N_PIX) return;

    int n = g_hcnt[p];
    g_hcnt[p] = 0;                 // reset for next graph replay (same thread: ordered)
    if (n > CAP) n = CAP;

    const float INF = __int_as_float(0x7f800000);
    float zk[TOPK], ak[TOPK], ck[TOPK];
#pragma unroll
    for (int k = 0; k < TOPK; k++) { zk[k] = INF; ak[k] = 0.0f; ck[k] = 0.0f; }

    const float4* __restrict__ src = g_hits[p];
#pragma unroll 2
    for (int j = 0; j < n; j++) {
        float4 h = src[j];
        float nz = h.x, na = h.y, nc = h.z;
#pragma unroll
        for (int k = 0; k < TOPK; k++) {
            if (nz < zk[k]) {
                float t;
                t = zk[k]; zk[k] = nz; nz = t;
                t = ak[k]; ak[k] = na; na = t;
                t = ck[k]; ck[k] = nc; nc = t;
            }
        }
    }

    // front-to-back over-composite (empty slots contribute 0)
    float trans = 1.0f, pixv = 0.0f;
#pragma unroll
    for (int k = 0; k < TOPK; k++) {
        pixv += ak[k] * trans * ck[k];
        trans *= (1.0f - ak[k]);
    }

    int base = p * 3;
    out[base + 0] = pixv;
    out[base + 1] = pixv;
    out[base + 2] = pixv;
}

extern "C" void kernel_launch(void* const* d_in, const int* in_sizes, int n_in,
                              void* d_out, int out_size) {
    const float* pcd         = (const float*)d_in[0];
    const float* displace    = (const float*)d_in[1];
    const float* init_colors = (const float*)d_in[2];
    float* out = (float*)d_out;

    // colors_ tail lives after the 4*128*128*3 image block
    float* out_colors = out + (size_t)N_PIX * 3;

    prep_kernel<<<(N_POINTS * N_VIEWS + 127) / 128, 128>>>(pcd, displace, init_colors, out_colors);
    raster_kernel<<<N_PIX / 256, 256>>>(out);
}

// round 9
// speedup vs baseline: 1.6216x; 1.3383x over previous
#include <cuda_runtime.h>
#include <math.h>

// Problem constants
#define N_POINTS 4096
#define N_VIEWS  4
#define IMG_H    128
#define IMG_W    128
#define N_PIX    (N_VIEWS * IMG_H * IMG_W)   // 65536
#define TOPK     5
#define R2F      0.0004f     // 0.02^2
#define CAP      40          // per-pixel hit capacity (avg ~4 in covered region, max ~20)

// cos(15deg), sin(15deg)
#define CE 0.96592582628906831f
#define SE 0.25881904510252074f

// Camera axes per view (columns of R): X_view = pcd . axis + T, T = (0,0,1.5)
__constant__ float c_ax[N_VIEWS][3] = {
    {-1.f, 0.f, 0.f}, {0.f, 0.f, 1.f}, {1.f, 0.f, 0.f}, {0.f, 0.f, -1.f}};
__constant__ float c_ay[N_VIEWS][3] = {
    {0.f, CE, -SE}, {-SE, CE, 0.f}, {0.f, CE, SE}, {SE, CE, 0.f}};
__constant__ float c_az[N_VIEWS][3] = {
    {0.f, -SE, -CE}, {-CE, -SE, 0.f}, {0.f, -SE, CE}, {CE, -SE, 0.f}};

// Plane-major per-pixel hit lists: hit j of pixel p at g_hits[j][p].
// (z, alpha, color, pad). Coalesced per-plane reads in raster.
__device__ float4 g_hits[CAP][N_PIX];
__device__ int    g_hcnt[N_PIX];      // zero-init at load; raster resets after read

// One thread per (point, view). 4 consecutive threads share a point.
__global__ void prep_kernel(const float* __restrict__ pcd,
                            const float* __restrict__ displace,
                            const float* __restrict__ init_colors,
                            float* __restrict__ out_colors) {
    int t = blockIdx.x * blockDim.x + threadIdx.x;
    if (t >= N_POINTS * N_VIEWS) return;
    int n = t >> 2;
    int v = t & 3;

    float x = pcd[3 * n + 0];
    float y = pcd[3 * n + 1];
    float z = pcd[3 * n + 2];
    float col = 1.0f / (1.0f + expf(-(init_colors[n] + displace[n])));
    if (v == 0) out_colors[n] = col;

    float px = x * c_ax[v][0] + y * c_ax[v][1] + z * c_ax[v][2];
    float py = x * c_ay[v][0] + y * c_ay[v][1] + z * c_ay[v][2];
    float zv = x * c_az[v][0] + y * c_az[v][1] + z * c_az[v][2] + 1.5f;
    float pz = (zv - 0.01f) / 99.99f;
    if (pz <= 0.0f) return;

    // pixel-center bbox: xf(xi) = 1 - (2xi+1)/128; disk spans <= 3 centers/axis
    const float rexp = 0.0201f;
    int ilo = max(0,   (int)ceilf ((1.0f - px - rexp) * 64.0f - 0.5f));
    int ihi = min(127, (int)floorf((1.0f - px + rexp) * 64.0f - 0.5f));
    int jlo = max(0,   (int)ceilf ((1.0f - py - rexp) * 64.0f - 0.5f));
    int jhi = min(127, (int)floorf((1.0f - py + rexp) * 64.0f - 0.5f));

    const float inv128 = 0.0078125f;

    // Fully unrolled 3x3 predicated scatter: 9 independent tests,
    // independent atomics issued back-to-back (latency overlapped).
    int   pp[9];
    float aa[9];
    bool  ok[9];
#pragma unroll
    for (int dj = 0; dj < 3; dj++) {
        int yi = jlo + dj;
        float yf = 1.0f - (float)(2 * yi + 1) * inv128;
        float dy = py - yf;
        float dy2 = dy * dy;
#pragma unroll
        for (int di = 0; di < 3; di++) {
            int e = dj * 3 + di;
            int xi = ilo + di;
            float xf = 1.0f - (float)(2 * xi + 1) * inv128;
            float dx = px - xf;
            float d2 = fmaf(dx, dx, dy2);
            ok[e] = (yi <= jhi) && (xi <= ihi) && (d2 < R2F);
            pp[e] = ((v * IMG_H) + yi) * IMG_W + xi;
            aa[e] = 1.0f - d2 / R2F;
        }
    }
    int ss[9];
#pragma unroll
    for (int e = 0; e < 9; e++)
        ss[e] = ok[e] ? atomicAdd(&g_hcnt[pp[e]], 1) : CAP;
#pragma unroll
    for (int e = 0; e < 9; e++)
        if (ss[e] < CAP)
            g_hits[ss[e]][pp[e]] = make_float4(pz, aa[e], col, 0.0f);
}

// One thread per pixel: gather own hits (plane-major, coalesced), top-5, composite.
__global__ void __launch_bounds__(128) raster_kernel(float* __restrict__ out) {
    int p = blockIdx.x * 128 + threadIdx.x;

    // count and plane-0 hit load concurrently (independent addresses)
    int n = g_hcnt[p];
    float4 h0 = g_hits[0][p];
    g_hcnt[p] = 0;                 // reset for next graph replay (same thread: ordered)
    if (n > CAP) n = CAP;

    const float INF = __int_as_float(0x7f800000);
    float zk[TOPK], ak[TOPK], ck[TOPK];
#pragma unroll
    for (int k = 0; k < TOPK; k++) { zk[k] = INF; ak[k] = 0.0f; ck[k] = 0.0f; }

    if (n > 0) { zk[0] = h0.x; ak[0] = h0.y; ck[0] = h0.z; }

    // remaining hits (rare: ~5% of pixels)
    for (int j = 1; j < n; j++) {
        float4 h = g_hits[j][p];
        float nz = h.x, na = h.y, nc = h.z;
#pragma unroll
        for (int k = 0; k < TOPK; k++) {
            if (nz < zk[k]) {
                float t;
                t = zk[k]; zk[k] = nz; nz = t;
                t = ak[k]; ak[k] = na; na = t;
                t = ck[k]; ck[k] = nc; nc = t;
            }
        }
    }

    // front-to-back over-composite (empty slots contribute 0)
    float trans = 1.0f, pixv = 0.0f;
#pragma unroll
    for (int k = 0; k < TOPK; k++) {
        pixv += ak[k] * trans * ck[k];
        trans *= (1.0f - ak[k]);
    }

    int base = p * 3;
    out[base + 0] = pixv;
    out[base + 1] = pixv;
    out[base + 2] = pixv;
}

extern "C" void kernel_launch(void* const* d_in, const int* in_sizes, int n_in,
                              void* d_out, int out_size) {
    const float* pcd         = (const float*)d_in[0];
    const float* displace    = (const float*)d_in[1];
    const float* init_colors = (const float*)d_in[2];
    float* out = (float*)d_out;

    // colors_ tail lives after the 4*128*128*3 image block
    float* out_colors = out + (size_t)N_PIX * 3;

    prep_kernel<<<(N_POINTS * N_VIEWS + 127) / 128, 128>>>(pcd, displace, init_colors, out_colors);
    raster_kernel<<<N_PIX / 128, 128>>>(out);
}